// round 7
// baseline (speedup 1.0000x reference)
#include <cuda_runtime.h>
#include <cuda_fp16.h>
#include <mma.h>
#include <cstdint>

using namespace nvcuda;

#define N_NODES 50000
#define PAD_NODES 50048      // 391 * 128 — GEMM epilogues store unguarded
#define N_EDGES 800000
#define F_IN    512
#define F_HID   128
#define F_OUT   64
#define NBLK    196          // ceil(50000/256)

// ---------------- device scratch (static; no allocation allowed) -------------
__device__ int    g_indeg[N_NODES];
__device__ int    g_outdeg[N_NODES];
__device__ float  g_outnorm[N_NODES];
__device__ float  g_innorm[N_NODES];
__device__ int    g_blk_agg[NBLK];
__device__ int    g_blk_flag[NBLK];
__device__ int    g_off[N_NODES + 1];
__device__ int    g_cursor[N_NODES];
__device__ int    g_csr[N_EDGES];
__device__ __half g_y1h[(size_t)PAD_NODES * F_HID];
__device__ __half g_hh [(size_t)N_NODES  * F_HID];
__device__ __half g_y2h[(size_t)PAD_NODES * F_OUT];

__device__ __forceinline__ float tf32_rna_f(float f) {
    uint32_t r; asm("cvt.rna.tf32.f32 %0, %1;" : "=r"(r) : "f"(f));
    return __uint_as_float(r);
}

// ---------------- degree init ------------------------------------------------
__global__ void k_zero_deg() {
    int i = blockIdx.x * blockDim.x + threadIdx.x;
    if (i < N_NODES) { g_indeg[i] = 0; g_outdeg[i] = 0; }
    if (i < NBLK)    { g_blk_flag[i] = 0; }
}

__global__ void k_degrees(const int* __restrict__ esrc, const int* __restrict__ edst) {
    int e = blockIdx.x * blockDim.x + threadIdx.x;
    if (e < N_EDGES) {
        atomicAdd(&g_outdeg[esrc[e]], 1);
        atomicAdd(&g_indeg [edst[e]], 1);
    }
}

// ---------------- fused scan: offsets + cursor + norms in ONE kernel ---------
__global__ void k_scan_fused() {
    __shared__ int sh[256];
    __shared__ int s_prefix;
    const int t = threadIdx.x;
    const int b = blockIdx.x;
    const int i = b * 256 + t;

    int v = (i < N_NODES) ? g_indeg[i] : 0;
    sh[t] = v;
    __syncthreads();
    #pragma unroll
    for (int o = 1; o < 256; o <<= 1) {
        int x = (t >= o) ? sh[t - o] : 0;
        __syncthreads();
        sh[t] += x;
        __syncthreads();
    }
    if (t == 255) {
        *(volatile int*)&g_blk_agg[b] = sh[255];
        __threadfence();
        *(volatile int*)&g_blk_flag[b] = 1;
    }
    if (t < 32) {
        int sum = 0;
        for (int w0 = 0; w0 < b; w0 += 32) {
            int idx = w0 + t;
            int val = 0;
            if (idx < b) {
                while (*(volatile int*)&g_blk_flag[idx] == 0) { }
                val = *(volatile int*)&g_blk_agg[idx];
            }
            #pragma unroll
            for (int o = 16; o > 0; o >>= 1)
                val += __shfl_xor_sync(0xFFFFFFFFu, val, o);
            sum += val;
        }
        if (t == 0) s_prefix = sum;
    }
    __syncthreads();
    if (i < N_NODES) {
        int incl = sh[t] + s_prefix;
        g_off[i + 1] = incl;
        g_cursor[i]  = incl - v;
        if (i == 0) g_off[0] = 0;
        g_outnorm[i] = rsqrtf(fmaxf((float)g_outdeg[i], 1.0f));
        g_innorm [i] = rsqrtf(fmaxf((float)v, 1.0f));
    }
}

__global__ void k_scatter(const int* __restrict__ esrc, const int* __restrict__ edst) {
    int e = blockIdx.x * blockDim.x + threadIdx.x;
    if (e < N_EDGES) {
        int d = edst[e];
        int p = atomicAdd(&g_cursor[d], 1);
        g_csr[p] = esrc[e];
    }
}

// ---------------- WMMA tf32 GEMM (R4 mainloop, fp16 output, 2-wave epilogue) -
// Y_half[M,BN] = ((A * outnorm[:,None]) @ W); A fp32 (L1) or fp16 g_hh (L2).
// BM=128, BK=32, 256 thr / 8 warps (4M x 2N), warp tile 32 x BN/2.
// Static smem only (37KB for BN=128) -> 5-6 CTAs/SM.
template <int BN, int KT, int LAYER>
__global__ void __launch_bounds__(256) k_wmma_gemm(const float* __restrict__ Ain,
                                                   const float* __restrict__ W) {
    constexpr int BM  = 128;
    constexpr int BK  = 32;
    constexpr int LDA = 40;
    constexpr int LDB = BN + 4;
    constexpr int WN  = BN / 2;
    constexpr int FN  = WN / 16;
    constexpr int SMEM_FLOATS = BM * LDA + BK * LDB;
    static_assert(4 * 32 * WN <= SMEM_FLOATS, "epilogue wave must fit");

    __shared__ float smem[SMEM_FLOATS];
    float* sA = smem;
    float* sB = smem + BM * LDA;

    const int tid  = threadIdx.x;
    const int wid  = tid >> 5;
    const int lane = tid & 31;
    const int wm   = wid >> 1;
    const int wn   = wid & 1;
    const int m0   = blockIdx.x * BM;

    wmma::fragment<wmma::accumulator, 16, 16, 8, float> c[2][FN];
    #pragma unroll
    for (int i = 0; i < 2; i++)
        #pragma unroll
        for (int j = 0; j < FN; j++) wmma::fill_fragment(c[i][j], 0.0f);

    const int arow  = tid >> 1;
    const int acol0 = (tid & 1) * 16;
    const int growA = m0 + arow;
    const bool okA  = growA < N_NODES;
    const float sc  = okA ? g_outnorm[growA] : 0.0f;

    for (int k0 = 0; k0 < KT; k0 += BK) {
        __syncthreads();
        // --- stage A (scaled + tf32-rounded) ---
        if constexpr (LAYER == 1) {
            const float* Arow = Ain + (size_t)growA * KT + k0 + acol0;
            #pragma unroll
            for (int q = 0; q < 4; q++) {
                float4 v = okA ? *(const float4*)(Arow + q * 4)
                               : make_float4(0.f, 0.f, 0.f, 0.f);
                float4 t;
                t.x = tf32_rna_f(v.x * sc);
                t.y = tf32_rna_f(v.y * sc);
                t.z = tf32_rna_f(v.z * sc);
                t.w = tf32_rna_f(v.w * sc);
                *(float4*)&sA[arow * LDA + acol0 + q * 4] = t;
            }
        } else {
            const __half* Arow = g_hh + (size_t)growA * KT + k0 + acol0;
            #pragma unroll
            for (int q = 0; q < 2; q++) {
                uint4 u = okA ? *(const uint4*)(Arow + q * 8)
                              : make_uint4(0u, 0u, 0u, 0u);
                const uint32_t uu[4] = { u.x, u.y, u.z, u.w };
                #pragma unroll
                for (int p = 0; p < 4; p++) {
                    float2 f = __half22float2(*(const __half2*)&uu[p]);
                    float2 t;
                    t.x = tf32_rna_f(f.x * sc);
                    t.y = tf32_rna_f(f.y * sc);
                    *(float2*)&sA[arow * LDA + acol0 + q * 8 + p * 2] = t;
                }
            }
        }
        // --- stage B (tf32-rounded); W is [KT x BN] row-major ---
        #pragma unroll
        for (int i = tid; i < BK * (BN / 4); i += 256) {
            int r = i / (BN / 4);
            int cc = (i % (BN / 4)) * 4;
            float4 v = *(const float4*)&W[(size_t)(k0 + r) * BN + cc];
            float4 t;
            t.x = tf32_rna_f(v.x);
            t.y = tf32_rna_f(v.y);
            t.z = tf32_rna_f(v.z);
            t.w = tf32_rna_f(v.w);
            *(float4*)&sB[r * LDB + cc] = t;
        }
        __syncthreads();

        // --- compute ---
        #pragma unroll
        for (int kk = 0; kk < BK; kk += 8) {
            wmma::fragment<wmma::matrix_a, 16, 16, 8, wmma::precision::tf32, wmma::row_major> a[2];
            wmma::fragment<wmma::matrix_b, 16, 16, 8, wmma::precision::tf32, wmma::row_major> bf[FN];
            #pragma unroll
            for (int i = 0; i < 2; i++)
                wmma::load_matrix_sync(a[i], &sA[(wm * 32 + i * 16) * LDA + kk], LDA);
            #pragma unroll
            for (int j = 0; j < FN; j++)
                wmma::load_matrix_sync(bf[j], &sB[kk * LDB + wn * WN + j * 16], LDB);
            #pragma unroll
            for (int i = 0; i < 2; i++)
                #pragma unroll
                for (int j = 0; j < FN; j++)
                    wmma::mma_sync(c[i][j], a[i], bf[j], c[i][j]);
        }
    }

    // --- epilogue: two waves of 4 warps stage through smem, emit half2 ---
    __half* Yh = (LAYER == 1) ? g_y1h : g_y2h;
    #pragma unroll
    for (int wave = 0; wave < 2; wave++) {
        __syncthreads();           // prior smem use (mainloop or wave 0) done
        if ((wid >> 2) == wave) {
            float* wtile = smem + (wid & 3) * (32 * WN);
            #pragma unroll
            for (int i = 0; i < 2; i++)
                #pragma unroll
                for (int j = 0; j < FN; j++)
                    wmma::store_matrix_sync(wtile + i * 16 * WN + j * 16,
                                            c[i][j], WN, wmma::mem_row_major);
            __syncwarp();
            const float* srow = wtile + lane * WN;
            __half* drow = Yh + (size_t)(m0 + wm * 32 + lane) * BN + wn * WN;
            #pragma unroll
            for (int k2 = 0; k2 < WN / 2; k2++) {
                float2 f = *(const float2*)(srow + k2 * 2);
                *(__half2*)(drow + k2 * 2) = __float22half2_rn(f);
            }
        }
    }
}

// ---------------- aggregation (CSR gather, fp16 payload) ---------------------
__global__ void __launch_bounds__(256) k_agg1(const float* __restrict__ b1) {
    int warp = (blockIdx.x * blockDim.x + threadIdx.x) >> 5;
    int lane = threadIdx.x & 31;
    if (warp >= N_NODES) return;
    int beg = g_off[warp], end = g_off[warp + 1];
    float4 acc = make_float4(0.f, 0.f, 0.f, 0.f);
    int j = beg;
    for (; j + 2 <= end; j += 2) {
        int s0 = g_csr[j], s1 = g_csr[j + 1];
        uint2 u0 = *(const uint2*)&g_y1h[(size_t)s0 * F_HID + lane * 4];
        uint2 u1 = *(const uint2*)&g_y1h[(size_t)s1 * F_HID + lane * 4];
        float2 a0 = __half22float2(*(const __half2*)&u0.x);
        float2 a1 = __half22float2(*(const __half2*)&u0.y);
        float2 b0 = __half22float2(*(const __half2*)&u1.x);
        float2 b1v = __half22float2(*(const __half2*)&u1.y);
        acc.x += a0.x + b0.x; acc.y += a0.y + b0.y;
        acc.z += a1.x + b1v.x; acc.w += a1.y + b1v.y;
    }
    if (j < end) {
        int s = g_csr[j];
        uint2 u = *(const uint2*)&g_y1h[(size_t)s * F_HID + lane * 4];
        float2 f0 = __half22float2(*(const __half2*)&u.x);
        float2 f1 = __half22float2(*(const __half2*)&u.y);
        acc.x += f0.x; acc.y += f0.y; acc.z += f1.x; acc.w += f1.y;
    }
    float inn = g_innorm[warp];
    float4 bb = *(const float4*)&b1[lane * 4];
    float2 o0, o1;
    o0.x = fmaxf(fmaf(acc.x, inn, bb.x), 0.f);
    o0.y = fmaxf(fmaf(acc.y, inn, bb.y), 0.f);
    o1.x = fmaxf(fmaf(acc.z, inn, bb.z), 0.f);
    o1.y = fmaxf(fmaf(acc.w, inn, bb.w), 0.f);
    uint2 u;
    *(__half2*)&u.x = __float22half2_rn(o0);
    *(__half2*)&u.y = __float22half2_rn(o1);
    *(uint2*)&g_hh[(size_t)warp * F_HID + lane * 4] = u;
}

__global__ void __launch_bounds__(256) k_agg2(const float* __restrict__ b2,
                                              float* __restrict__ out) {
    int warp = (blockIdx.x * blockDim.x + threadIdx.x) >> 5;
    int lane = threadIdx.x & 31;
    if (warp >= N_NODES) return;
    int beg = g_off[warp], end = g_off[warp + 1];
    float2 acc = make_float2(0.f, 0.f);
    int j = beg;
    for (; j + 2 <= end; j += 2) {
        int s0 = g_csr[j], s1 = g_csr[j + 1];
        float2 f0 = __half22float2(*(const __half2*)&g_y2h[(size_t)s0 * F_OUT + lane * 2]);
        float2 f1 = __half22float2(*(const __half2*)&g_y2h[(size_t)s1 * F_OUT + lane * 2]);
        acc.x += f0.x + f1.x; acc.y += f0.y + f1.y;
    }
    if (j < end) {
        float2 f = __half22float2(*(const __half2*)&g_y2h[(size_t)g_csr[j] * F_OUT + lane * 2]);
        acc.x += f.x; acc.y += f.y;
    }
    float inn = g_innorm[warp];
    float2 bb = *(const float2*)&b2[lane * 2];
    float2 o;
    o.x = fmaf(acc.x, inn, bb.x);
    o.y = fmaf(acc.y, inn, bb.y);
    *(float2*)&out[(size_t)warp * F_OUT + lane * 2] = o;
}

// ---------------- launch -----------------------------------------------------
extern "C" void kernel_launch(void* const* d_in, const int* in_sizes, int n_in,
                              void* d_out, int out_size) {
    const float* features = (const float*)d_in[0];
    const int*   esrc     = (const int*)  d_in[1];
    const int*   edst     = (const int*)  d_in[2];
    const float* W1       = (const float*)d_in[3];
    const float* b1       = (const float*)d_in[4];
    const float* W2       = (const float*)d_in[5];
    const float* b2       = (const float*)d_in[6];
    float* out = (float*)d_out;

    const int EB = (N_EDGES + 255) / 256;     // 3125
    const int GB = (N_NODES + 127) / 128;     // 391

    k_zero_deg  <<<NBLK, 256>>>();
    k_degrees   <<<EB, 256>>>(esrc, edst);
    k_scan_fused<<<NBLK, 256>>>();
    k_scatter   <<<EB, 256>>>(esrc, edst);

    k_wmma_gemm<128, 512, 1><<<GB, 256>>>(features, W1);
    k_agg1<<<(N_NODES * 32 + 255) / 256, 256>>>(b1);
    k_wmma_gemm<64, 128, 2><<<GB, 256>>>(nullptr, W2);
    k_agg2<<<(N_NODES * 32 + 255) / 256, 256>>>(b2, out);
}

// round 10
// speedup vs baseline: 1.6368x; 1.6368x over previous
#include <cuda_runtime.h>
#include <cuda_bf16.h>
#include <mma.h>
#include <cstdint>

using namespace nvcuda;

#define N_NODES 50000
#define PAD_NODES 50048      // 391 * 128, so GEMM epilogues can store unguarded
#define N_EDGES 800000
#define F_IN    512
#define F_HID   128
#define F_OUT   64
#define NBLK    196          // ceil(50000/256)

// ---------------- device scratch (static; no allocation allowed) -------------
__device__ int   g_indeg[N_NODES];
__device__ int   g_outdeg[N_NODES];
__device__ float g_outnorm[N_NODES];
__device__ float g_innorm[N_NODES];
__device__ int   g_blk_agg[NBLK];
__device__ int   g_blk_flag[NBLK];
__device__ int   g_off[N_NODES + 1];
__device__ int   g_cursor[N_NODES];
__device__ int   g_csr[N_EDGES];
__device__ float g_y1[(size_t)PAD_NODES * F_HID];
__device__ float g_h [(size_t)N_NODES  * F_HID];
__device__ float g_y2[(size_t)PAD_NODES * F_OUT];

__device__ __forceinline__ float tf32_rna_f(float f) {
    uint32_t r; asm("cvt.rna.tf32.f32 %0, %1;" : "=r"(r) : "f"(f));
    return __uint_as_float(r);
}

// ---------------- degree / CSR construction --------------------------------
__global__ void k_zero_deg() {
    int i = blockIdx.x * blockDim.x + threadIdx.x;
    if (i < N_NODES) { g_indeg[i] = 0; g_outdeg[i] = 0; }
    if (i < NBLK)    { g_blk_flag[i] = 0; }
}

__global__ void k_degrees(const int* __restrict__ esrc, const int* __restrict__ edst) {
    int e = blockIdx.x * blockDim.x + threadIdx.x;
    if (e < N_EDGES) {
        atomicAdd(&g_outdeg[esrc[e]], 1);
        atomicAdd(&g_indeg [edst[e]], 1);
    }
}

// fused scan: per-block scan + publish aggregate + warp-window lookback,
// then offsets, cursor, and norms — one kernel instead of three.
__global__ void k_scan_fused() {
    __shared__ int sh[256];
    __shared__ int s_prefix;
    const int t = threadIdx.x;
    const int b = blockIdx.x;
    const int i = b * 256 + t;

    int v = (i < N_NODES) ? g_indeg[i] : 0;
    sh[t] = v;
    __syncthreads();
    #pragma unroll
    for (int o = 1; o < 256; o <<= 1) {
        int x = (t >= o) ? sh[t - o] : 0;
        __syncthreads();
        sh[t] += x;
        __syncthreads();
    }
    if (t == 255) {
        *(volatile int*)&g_blk_agg[b] = sh[255];
        __threadfence();
        *(volatile int*)&g_blk_flag[b] = 1;
    }
    if (t < 32) {
        int sum = 0;
        for (int w0 = 0; w0 < b; w0 += 32) {
            int idx = w0 + t;
            int val = 0;
            if (idx < b) {
                while (*(volatile int*)&g_blk_flag[idx] == 0) { }
                val = *(volatile int*)&g_blk_agg[idx];
            }
            #pragma unroll
            for (int o = 16; o > 0; o >>= 1)
                val += __shfl_xor_sync(0xFFFFFFFFu, val, o);
            sum += val;
        }
        if (t == 0) s_prefix = sum;
    }
    __syncthreads();
    if (i < N_NODES) {
        int incl = sh[t] + s_prefix;
        g_off[i + 1] = incl;
        g_cursor[i]  = incl - v;
        if (i == 0) g_off[0] = 0;
        g_outnorm[i] = rsqrtf(fmaxf((float)g_outdeg[i], 1.0f));
        g_innorm [i] = rsqrtf(fmaxf((float)v, 1.0f));
    }
}

__global__ void k_scatter(const int* __restrict__ esrc, const int* __restrict__ edst) {
    int e = blockIdx.x * blockDim.x + threadIdx.x;
    if (e < N_EDGES) {
        int d = edst[e];
        int p = atomicAdd(&g_cursor[d], 1);
        g_csr[p] = esrc[e];
    }
}

// ---------------- WMMA tf32 GEMM: Y = (A * outnorm[:,None]) @ W -------------
// (exact R4 structure: static smem, serialized stage+compute, direct fp32
//  store_matrix_sync epilogue)
template <int BN, int KT, int LAYER>
__global__ void __launch_bounds__(256) k_wmma_gemm(const float* __restrict__ Ain,
                                                   const float* __restrict__ W) {
    constexpr int BM  = 128;
    constexpr int BK  = 32;
    constexpr int LDA = 40;
    constexpr int LDB = BN + 4;
    constexpr int WN  = BN / 2;
    constexpr int FN  = WN / 16;

    const float* A = (LAYER == 2) ? (const float*)g_h : Ain;
    float* Y = (LAYER == 1) ? g_y1 : g_y2;

    __shared__ float sA[BM * LDA];
    __shared__ float sB[BK * LDB];

    const int tid  = threadIdx.x;
    const int wid  = tid >> 5;
    const int wm   = wid >> 1;
    const int wn   = wid & 1;
    const int m0   = blockIdx.x * BM;

    wmma::fragment<wmma::accumulator, 16, 16, 8, float> c[2][FN];
    #pragma unroll
    for (int i = 0; i < 2; i++)
        #pragma unroll
        for (int j = 0; j < FN; j++) wmma::fill_fragment(c[i][j], 0.0f);

    const int arow  = tid >> 1;
    const int acol0 = (tid & 1) * 16;
    const int growA = m0 + arow;
    const bool okA  = growA < N_NODES;
    const float sc  = okA ? g_outnorm[growA] : 0.0f;
    const float* Arow = A + (size_t)growA * KT;

    for (int k0 = 0; k0 < KT; k0 += BK) {
        __syncthreads();
        #pragma unroll
        for (int q = 0; q < 4; q++) {
            float4 v = okA ? *(const float4*)(Arow + k0 + acol0 + q * 4)
                           : make_float4(0.f, 0.f, 0.f, 0.f);
            float4 t;
            t.x = tf32_rna_f(v.x * sc);
            t.y = tf32_rna_f(v.y * sc);
            t.z = tf32_rna_f(v.z * sc);
            t.w = tf32_rna_f(v.w * sc);
            *(float4*)&sA[arow * LDA + acol0 + q * 4] = t;
        }
        #pragma unroll
        for (int i = tid; i < BK * (BN / 4); i += 256) {
            int r = i / (BN / 4);
            int cc = (i % (BN / 4)) * 4;
            float4 v = *(const float4*)&W[(size_t)(k0 + r) * BN + cc];
            float4 t;
            t.x = tf32_rna_f(v.x);
            t.y = tf32_rna_f(v.y);
            t.z = tf32_rna_f(v.z);
            t.w = tf32_rna_f(v.w);
            *(float4*)&sB[r * LDB + cc] = t;
        }
        __syncthreads();

        #pragma unroll
        for (int kk = 0; kk < BK; kk += 8) {
            wmma::fragment<wmma::matrix_a, 16, 16, 8, wmma::precision::tf32, wmma::row_major> a[2];
            wmma::fragment<wmma::matrix_b, 16, 16, 8, wmma::precision::tf32, wmma::row_major> b[FN];
            #pragma unroll
            for (int i = 0; i < 2; i++)
                wmma::load_matrix_sync(a[i], &sA[(wm * 32 + i * 16) * LDA + kk], LDA);
            #pragma unroll
            for (int j = 0; j < FN; j++)
                wmma::load_matrix_sync(b[j], &sB[kk * LDB + wn * WN + j * 16], LDB);
            #pragma unroll
            for (int i = 0; i < 2; i++)
                #pragma unroll
                for (int j = 0; j < FN; j++)
                    wmma::mma_sync(c[i][j], a[i], b[j], c[i][j]);
        }
    }

    #pragma unroll
    for (int i = 0; i < 2; i++)
        #pragma unroll
        for (int j = 0; j < FN; j++) {
            float* dst = Y + (size_t)(m0 + wm * 32 + i * 16) * BN + wn * WN + j * 16;
            wmma::store_matrix_sync(dst, c[i][j], BN, wmma::mem_row_major);
        }
}

// ---------------- aggregation (CSR gather, fp32, MLP=2 unroll) ---------------
__global__ void __launch_bounds__(256) k_agg1(const float* __restrict__ b1) {
    int warp = (blockIdx.x * blockDim.x + threadIdx.x) >> 5;
    int lane = threadIdx.x & 31;
    if (warp >= N_NODES) return;
    int beg = g_off[warp], end = g_off[warp + 1];
    float4 acc = make_float4(0.f, 0.f, 0.f, 0.f);
    int j = beg;
    for (; j + 2 <= end; j += 2) {
        int s0 = g_csr[j], s1 = g_csr[j + 1];
        float4 v0 = *(const float4*)&g_y1[(size_t)s0 * F_HID + lane * 4];
        float4 v1 = *(const float4*)&g_y1[(size_t)s1 * F_HID + lane * 4];
        acc.x += v0.x + v1.x; acc.y += v0.y + v1.y;
        acc.z += v0.z + v1.z; acc.w += v0.w + v1.w;
    }
    if (j < end) {
        float4 v = *(const float4*)&g_y1[(size_t)g_csr[j] * F_HID + lane * 4];
        acc.x += v.x; acc.y += v.y; acc.z += v.z; acc.w += v.w;
    }
    float inn = g_innorm[warp];
    float4 bb = *(const float4*)&b1[lane * 4];
    float4 o;
    o.x = fmaxf(fmaf(acc.x, inn, bb.x), 0.f);
    o.y = fmaxf(fmaf(acc.y, inn, bb.y), 0.f);
    o.z = fmaxf(fmaf(acc.z, inn, bb.z), 0.f);
    o.w = fmaxf(fmaf(acc.w, inn, bb.w), 0.f);
    *(float4*)&g_h[(size_t)warp * F_HID + lane * 4] = o;
}

__global__ void __launch_bounds__(256) k_agg2(const float* __restrict__ b2,
                                              float* __restrict__ out) {
    int warp = (blockIdx.x * blockDim.x + threadIdx.x) >> 5;
    int lane = threadIdx.x & 31;
    if (warp >= N_NODES) return;
    int beg = g_off[warp], end = g_off[warp + 1];
    float2 acc = make_float2(0.f, 0.f);
    int j = beg;
    for (; j + 2 <= end; j += 2) {
        int s0 = g_csr[j], s1 = g_csr[j + 1];
        float2 v0 = *(const float2*)&g_y2[(size_t)s0 * F_OUT + lane * 2];
        float2 v1 = *(const float2*)&g_y2[(size_t)s1 * F_OUT + lane * 2];
        acc.x += v0.x + v1.x; acc.y += v0.y + v1.y;
    }
    if (j < end) {
        float2 v = *(const float2*)&g_y2[(size_t)g_csr[j] * F_OUT + lane * 2];
        acc.x += v.x; acc.y += v.y;
    }
    float inn = g_innorm[warp];
    float2 bb = *(const float2*)&b2[lane * 2];
    float2 o;
    o.x = fmaf(acc.x, inn, bb.x);
    o.y = fmaf(acc.y, inn, bb.y);
    *(float2*)&out[(size_t)warp * F_OUT + lane * 2] = o;
}

// ---------------- launch -----------------------------------------------------
extern "C" void kernel_launch(void* const* d_in, const int* in_sizes, int n_in,
                              void* d_out, int out_size) {
    const float* features = (const float*)d_in[0];
    const int*   esrc     = (const int*)  d_in[1];
    const int*   edst     = (const int*)  d_in[2];
    const float* W1       = (const float*)d_in[3];
    const float* b1       = (const float*)d_in[4];
    const float* W2       = (const float*)d_in[5];
    const float* b2       = (const float*)d_in[6];
    float* out = (float*)d_out;

    const int EB = (N_EDGES + 255) / 256;     // 3125
    const int GB = (N_NODES + 127) / 128;     // 391

    k_zero_deg  <<<NBLK, 256>>>();
    k_degrees   <<<EB, 256>>>(esrc, edst);
    k_scan_fused<<<NBLK, 256>>>();
    k_scatter   <<<EB, 256>>>(esrc, edst);

    k_wmma_gemm<128, 512, 1><<<GB, 256>>>(features, W1);
    k_agg1<<<(N_NODES * 32 + 255) / 256, 256>>>(b1);
    k_wmma_gemm<64, 128, 2><<<GB, 256>>>(nullptr, W2);
    k_agg2<<<(N_NODES * 32 + 255) / 256, 256>>>(b2, out);
}